// round 3
// baseline (speedup 1.0000x reference)
#include <cuda_runtime.h>
#include <cuda_bf16.h>

// Problem constants
#define MAXN 100000
#define MAXE 1600000

// ---------------- scratch (device globals — no runtime allocation) ----------
__device__ int   g_is64;            // 1 if ei_feat is int64, 0 if int32
__device__ int   g_cnt[MAXN];
__device__ float g_dinv[MAXN];
__device__ int   g_off[MAXN + 1];
__device__ int   g_cur[MAXN];
__device__ int   g_csr[MAXE];
__device__ int   g_bsum[256];
__device__ int   g_bscan[256];
__device__ float g_Xs[MAXN * 64];   // dinv[n] * X[n]
__device__ float g_Xt[MAXN * 64];   // aggregated layer-1 input
__device__ float g_H [MAXN * 256];  // elu(Xt @ Wblk + b)
__device__ float g_Fp[MAXN * 64];   // dinv[n] * (H @ W_fuse)

// ---------------- helpers ---------------------------------------------------
__device__ __forceinline__ void add4(float4& a, const float4 b) {
    a.x += b.x; a.y += b.y; a.z += b.z; a.w += b.w;
}

__device__ __forceinline__ int clampN(int v, int N) {
    v = v < 0 ? 0 : v;
    return v >= N ? N - 1 : v;
}

// Read edge endpoint idx from ei buffer honoring detected dtype.
__device__ __forceinline__ int edge_at(const void* ei, int idx) {
    if (g_is64) return (int)((const long long*)ei)[idx];
    return ((const int*)ei)[idx];
}

// ---------------- dtype detection -------------------------------------------
// If ei is int64, every value < 2^31, so odd 32-bit words (high halves of the
// first E entries) are all zero. If int32, odd words are src[1],src[3],...
// (random node ids, overwhelmingly nonzero). Inspect only the first 2048
// words, which is within the guaranteed 2E-word allocation either way.
__global__ void k_detect(const unsigned int* __restrict__ w, int E) {
    if (threadIdx.x == 0 && blockIdx.x == 0) g_is64 = 1;
    __syncthreads();
    int npairs = E < 1024 ? E : 1024;
    int i = threadIdx.x;
    if (i < npairs) {
        if (w[2 * i + 1] != 0u) atomicExch(&g_is64, 0);
    }
}

// ---------------- CSR build -------------------------------------------------
__global__ void k_zero_cnt(int N) {
    for (int i = blockIdx.x * blockDim.x + threadIdx.x; i < N;
         i += gridDim.x * blockDim.x)
        g_cnt[i] = 0;
}

__global__ void k_hist(const void* __restrict__ ei, int E, int N) {
    int e = blockIdx.x * blockDim.x + threadIdx.x;
    if (e < E) {
        int dst = clampN(edge_at(ei, E + e), N);
        atomicAdd(&g_cnt[dst], 1);
    }
}

// block-local exclusive scan (1024/block) + per-block sums; also dinv
__global__ void k_scan1(int N) {
    __shared__ int s[1024];
    int tid = threadIdx.x;
    int i = blockIdx.x * 1024 + tid;
    int v = (i < N) ? g_cnt[i] : 0;
    s[tid] = v;
    __syncthreads();
    for (int o = 1; o < 1024; o <<= 1) {
        int t = (tid >= o) ? s[tid - o] : 0;
        __syncthreads();
        s[tid] += t;
        __syncthreads();
    }
    if (i < N) {
        g_off[i] = s[tid] - v;                     // exclusive, block-local
        g_dinv[i] = rsqrtf((float)(v + 1));        // +1 for self-loop
    }
    if (tid == 1023) g_bsum[blockIdx.x] = s[1023];
}

__global__ void k_scan2(int NB) {
    __shared__ int s[128];
    int tid = threadIdx.x;
    int v = (tid < NB) ? g_bsum[tid] : 0;
    s[tid] = v;
    __syncthreads();
    for (int o = 1; o < 128; o <<= 1) {
        int t = (tid >= o) ? s[tid - o] : 0;
        __syncthreads();
        s[tid] += t;
        __syncthreads();
    }
    if (tid < NB) g_bscan[tid] = s[tid] - v;
}

__global__ void k_scan3(int N, int E) {
    int i = blockIdx.x * 1024 + threadIdx.x;
    if (i < N) {
        int v = g_off[i] + g_bscan[blockIdx.x];
        g_off[i] = v;
        g_cur[i] = v;
    }
    if (i == 0) g_off[N] = E;
}

__global__ void k_fill(const void* __restrict__ ei, int E, int N) {
    int e = blockIdx.x * blockDim.x + threadIdx.x;
    if (e < E) {
        int dst = clampN(edge_at(ei, E + e), N);
        int src = clampN(edge_at(ei, e), N);
        int pos = atomicAdd(&g_cur[dst], 1);
        if (pos < MAXE) g_csr[pos] = src;
    }
}

// ---------------- feature prep: Xs = dinv[n] * X[n] -------------------------
__global__ void k_prep(const float* __restrict__ X, int N) {
    int idx = blockIdx.x * blockDim.x + threadIdx.x;   // float4 units
    int total = N * 16;
    if (idx < total) {
        int n = idx >> 4;
        float s = g_dinv[n];
        float4 v = ((const float4*)X)[idx];
        v.x *= s; v.y *= s; v.z *= s; v.w *= s;
        ((float4*)g_Xs)[idx] = v;
    }
}

// ---------------- aggregation: g_Xt[n] = dinv[n]*(g_Xs[n] + sum_neigh g_Xs) -
// 16 lanes per node, each lane owns one float4 of the 64-wide row.
__global__ void k_agg64(int N) {
    int tid = threadIdx.x;
    int lane = tid & 15;
    int n = blockIdx.x * 16 + (tid >> 4);
    if (n >= N) return;
    const float4* feat = (const float4*)g_Xs;
    int base = n * 16;
    float4 acc = feat[base + lane];                    // self-loop term
    int beg = g_off[n], end = g_off[n + 1];
    int j = beg;
    for (; j + 4 <= end; j += 4) {
        int u0 = g_csr[j];
        int u1 = g_csr[j + 1];
        int u2 = g_csr[j + 2];
        int u3 = g_csr[j + 3];
        float4 a = feat[u0 * 16 + lane];
        float4 b = feat[u1 * 16 + lane];
        float4 c = feat[u2 * 16 + lane];
        float4 d = feat[u3 * 16 + lane];
        add4(acc, a); add4(acc, b); add4(acc, c); add4(acc, d);
    }
    for (; j < end; ++j) {
        int u = g_csr[j];
        add4(acc, feat[u * 16 + lane]);
    }
    float s = g_dinv[n];
    acc.x *= s; acc.y *= s; acc.z *= s; acc.w *= s;
    ((float4*)g_Xt)[base + lane] = acc;
}

// ---------------- GEMM1: H = elu(Xt @ blockdiag(Wn,Ws) + b) -----------------
// block = 256 threads = 4 nodes x 64 col-quads; weights in shared.
__global__ void k_gemm1(const float* __restrict__ Wn, const float* __restrict__ bn,
                        const float* __restrict__ Ws, const float* __restrict__ bs,
                        int N) {
    __shared__ float sW[8192];   // [0:4096)=Wn (k*128+j), [4096:8192)=Ws
    __shared__ float sX[4 * 64];
    int tid = threadIdx.x;
    for (int i = tid; i < 4096; i += 256) {
        sW[i]        = Wn[i];
        sW[4096 + i] = Ws[i];
    }
    {
        int n = blockIdx.x * 4 + (tid >> 6);
        sX[tid] = (n < N) ? g_Xt[n * 64 + (tid & 63)] : 0.0f;
    }
    __syncthreads();

    int nl = tid >> 6;              // node within block
    int jq = tid & 63;              // col quad 0..63 -> cols 4*jq of 256
    int hsel = jq >> 5;             // 0 = nuc, 1 = surf
    int j0 = (jq & 31) * 4;

    float x[32];
    const float* xp = &sX[nl * 64 + hsel * 32];
#pragma unroll
    for (int k = 0; k < 32; ++k) x[k] = xp[k];

    const float* wbase = &sW[hsel * 4096 + j0];
    float4 acc = {0.f, 0.f, 0.f, 0.f};
#pragma unroll
    for (int k = 0; k < 32; ++k) {
        float4 w = *(const float4*)&wbase[k * 128];
        acc.x += x[k] * w.x;
        acc.y += x[k] * w.y;
        acc.z += x[k] * w.z;
        acc.w += x[k] * w.w;
    }

    const float* bptr = hsel ? bs : bn;
    float4 b4 = *(const float4*)&bptr[j0];
    acc.x += b4.x; acc.y += b4.y; acc.z += b4.z; acc.w += b4.w;
    acc.x = acc.x > 0.f ? acc.x : (__expf(acc.x) - 1.0f);
    acc.y = acc.y > 0.f ? acc.y : (__expf(acc.y) - 1.0f);
    acc.z = acc.z > 0.f ? acc.z : (__expf(acc.z) - 1.0f);
    acc.w = acc.w > 0.f ? acc.w : (__expf(acc.w) - 1.0f);

    int n = blockIdx.x * 4 + nl;
    if (n < N)
        *(float4*)&g_H[n * 256 + hsel * 128 + j0] = acc;
}

// ---------------- GEMM2: Fp = dinv * (H @ W_fuse) ---------------------------
// 64 nodes x 64 cols per block; 4x4 register tile per thread; k chunked by 64.
__global__ void k_gemm2(const float* __restrict__ Wf, int N) {
    __shared__ float sH[64][65];
    __shared__ float sW[64][64];
    int tid = threadIdx.x;
    int tx = tid & 15;          // col quad
    int ty = tid >> 4;          // node quad
    int node0 = blockIdx.x * 64;

    float acc[4][4];
#pragma unroll
    for (int i = 0; i < 4; ++i)
#pragma unroll
        for (int jj = 0; jj < 4; ++jj) acc[i][jj] = 0.f;

    for (int kc = 0; kc < 4; ++kc) {
        for (int idx = tid; idx < 1024; idx += 256) {
            int r = idx >> 4, cq = idx & 15;
            float4 v = {0.f, 0.f, 0.f, 0.f};
            if (node0 + r < N)
                v = *(const float4*)&g_H[(node0 + r) * 256 + kc * 64 + cq * 4];
            sH[r][cq * 4 + 0] = v.x;
            sH[r][cq * 4 + 1] = v.y;
            sH[r][cq * 4 + 2] = v.z;
            sH[r][cq * 4 + 3] = v.w;
        }
        for (int idx = tid; idx < 1024; idx += 256) {
            int r = idx >> 4, cq = idx & 15;
            *(float4*)&sW[r][cq * 4] = *(const float4*)&Wf[(kc * 64 + r) * 64 + cq * 4];
        }
        __syncthreads();
#pragma unroll 8
        for (int k = 0; k < 64; ++k) {
            float4 w = *(const float4*)&sW[k][tx * 4];
            float xr[4];
#pragma unroll
            for (int i = 0; i < 4; ++i) xr[i] = sH[ty * 4 + i][k];
#pragma unroll
            for (int i = 0; i < 4; ++i) {
                acc[i][0] += xr[i] * w.x;
                acc[i][1] += xr[i] * w.y;
                acc[i][2] += xr[i] * w.z;
                acc[i][3] += xr[i] * w.w;
            }
        }
        __syncthreads();
    }

#pragma unroll
    for (int i = 0; i < 4; ++i) {
        int n = node0 + ty * 4 + i;
        if (n < N) {
            float s = g_dinv[n];
            float4 v = {acc[i][0] * s, acc[i][1] * s, acc[i][2] * s, acc[i][3] * s};
            *(float4*)&g_Fp[n * 64 + tx * 4] = v;
        }
    }
}

// ---------------- layer-2 aggregation + bias + softmax ----------------------
__global__ void k_agg_softmax(const float* __restrict__ bf, float* __restrict__ out, int N) {
    int tid = threadIdx.x;
    int lane = tid & 15;
    int n = blockIdx.x * 16 + (tid >> 4);
    if (n >= N) return;
    const float4* feat = (const float4*)g_Fp;
    int base = n * 16;
    float4 acc = feat[base + lane];                    // self-loop term
    int beg = g_off[n], end = g_off[n + 1];
    int j = beg;
    for (; j + 4 <= end; j += 4) {
        int u0 = g_csr[j];
        int u1 = g_csr[j + 1];
        int u2 = g_csr[j + 2];
        int u3 = g_csr[j + 3];
        float4 a = feat[u0 * 16 + lane];
        float4 b = feat[u1 * 16 + lane];
        float4 c = feat[u2 * 16 + lane];
        float4 d = feat[u3 * 16 + lane];
        add4(acc, a); add4(acc, b); add4(acc, c); add4(acc, d);
    }
    for (; j < end; ++j) {
        int u = g_csr[j];
        add4(acc, feat[u * 16 + lane]);
    }
    float s = g_dinv[n];
    float4 b4 = ((const float4*)bf)[lane];
    float4 z = {acc.x * s + b4.x, acc.y * s + b4.y,
                acc.z * s + b4.z, acc.w * s + b4.w};

    // softmax over 64 logits spread across 16 lanes (4 each)
    float m = fmaxf(fmaxf(z.x, z.y), fmaxf(z.z, z.w));
#pragma unroll
    for (int o = 8; o > 0; o >>= 1)
        m = fmaxf(m, __shfl_xor_sync(0xffffffffu, m, o, 16));
    z.x = __expf(z.x - m); z.y = __expf(z.y - m);
    z.z = __expf(z.z - m); z.w = __expf(z.w - m);
    float sum = z.x + z.y + z.z + z.w;
#pragma unroll
    for (int o = 8; o > 0; o >>= 1)
        sum += __shfl_xor_sync(0xffffffffu, sum, o, 16);
    float inv = 1.0f / sum;
    z.x *= inv; z.y *= inv; z.z *= inv; z.w *= inv;
    ((float4*)out)[base + lane] = z;
}

// ---------------- launch ----------------------------------------------------
extern "C" void kernel_launch(void* const* d_in, const int* in_sizes, int n_in,
                              void* d_out, int out_size) {
    const float* X  = (const float*)d_in[0];
    const void*  ei = d_in[1];            // int32 or int64 — detected on device
    // d_in[2] = batch (unused; all zeros)
    const float* Wn = (const float*)d_in[3];
    const float* bn = (const float*)d_in[4];
    const float* Ws = (const float*)d_in[5];
    const float* bs = (const float*)d_in[6];
    const float* Wf = (const float*)d_in[7];
    const float* bf = (const float*)d_in[8];
    float* out = (float*)d_out;

    int N = in_sizes[0] / 64;
    int E = in_sizes[1] / 2;
    int NB = (N + 1023) / 1024;

    k_detect<<<1, 1024>>>((const unsigned int*)ei, E);
    k_zero_cnt<<<256, 256>>>(N);
    k_hist<<<(E + 511) / 512, 512>>>(ei, E, N);
    k_scan1<<<NB, 1024>>>(N);
    k_scan2<<<1, 128>>>(NB);
    k_scan3<<<NB, 1024>>>(N, E);
    k_fill<<<(E + 511) / 512, 512>>>(ei, E, N);
    k_prep<<<(N * 16 + 255) / 256, 256>>>(X, N);
    k_agg64<<<(N + 15) / 16, 256>>>(N);
    k_gemm1<<<(N + 3) / 4, 256>>>(Wn, bn, Ws, bs, N);
    k_gemm2<<<(N + 63) / 64, 256>>>(Wf, N);
    k_agg_softmax<<<(N + 15) / 16, 256>>>(bf, out, N);
}